// round 13
// baseline (speedup 1.0000x reference)
#include <cuda_runtime.h>

#define Bb 2
#define Nn 16384
#define Mm 8192
#define Kk 2048
#define Rr 128

// ---------------- scratch (__device__ globals; no allocation allowed) ----------------
__device__ float g_px[Bb*Nn], g_py[Bb*Nn], g_pz[Bb*Nn];
__device__ float g_qx[Bb*Mm], g_qy[Bb*Mm], g_qz[Bb*Mm];
__device__ float g_fraw[Bb*Nn*32];
__device__ float g_fc3[Bb*Mm*64];
__device__ int   g_flag[Bb*Nn];
__device__ float g_cx[Bb*Nn], g_cy[Bb*Nn], g_cz[Bb*Nn];
__device__ int   g_vcount[Bb];
__device__ float g_kpx[Bb*Kk], g_kpy[Bb*Kk], g_kpz[Bb*Kk];
__device__ float g_feats[Bb*Kk*352];
__device__ float g_dov[Bb*Nn];                    // overflow distances (V > RCOV only)
__device__ int   g_bkt[Bb*Nn];                    // Morton bucket per point
__device__ float g_sx[Bb*Nn], g_sy[Bb*Nn], g_sz[Bb*Nn];  // spatially sorted coords
__device__ int   g_srank[Bb*Nn];                  // sorted pos -> original compacted rank

// packed f32x2 helpers (per-lane IEEE rn -> bitwise identical to scalar __fadd_rn/__fmul_rn)
__device__ __forceinline__ unsigned long long pk2(float lo, float hi) {
    unsigned long long r;
    asm("mov.b64 %0, {%1, %2};" : "=l"(r) : "f"(lo), "f"(hi));
    return r;
}
__device__ __forceinline__ void upk2(unsigned long long v, float& lo, float& hi) {
    asm("mov.b64 {%0, %1}, %2;" : "=f"(lo), "=f"(hi) : "l"(v));
}
__device__ __forceinline__ unsigned long long add2(unsigned long long a, unsigned long long b) {
    unsigned long long r;
    asm("add.rn.f32x2 %0, %1, %2;" : "=l"(r) : "l"(a), "l"(b));
    return r;
}
__device__ __forceinline__ unsigned long long mul2(unsigned long long a, unsigned long long b) {
    unsigned long long r;
    asm("mul.rn.f32x2 %0, %1, %2;" : "=l"(r) : "l"(a), "l"(b));
    return r;
}
__device__ __forceinline__ unsigned p1b1(unsigned x) {   // interleave bits with zeros
    x &= 0x0000ffffu;
    x = (x | (x << 8)) & 0x00FF00FFu;
    x = (x | (x << 4)) & 0x0F0F0F0Fu;
    x = (x | (x << 2)) & 0x33333333u;
    x = (x | (x << 1)) & 0x55555555u;
    return x;
}

// ---------------- ROI validity mask (bitwise-strict fp32, no contraction) ------------
__global__ void roi_mask_kernel(const float* __restrict__ points,
                                const float* __restrict__ bboxes) {
    int blk = blockIdx.x;                          // Bb*Nn/256 blocks, batch-aligned
    int b = blk / (Nn / 256);
    int t = threadIdx.x;
    __shared__ float rcx[Rr], rcy[Rr], rcz[Rr], rth[Rr];
    if (t < Rr) {
        const float* bb = bboxes + ((size_t)b * Rr + t) * 7;
        rcx[t] = bb[0]; rcy[t] = bb[1]; rcz[t] = bb[2];
        float hx = __fmul_rn(bb[3], 0.5f);
        float hy = __fmul_rn(bb[4], 0.5f);
        float hz = __fmul_rn(bb[5], 0.5f);
        float s = __fadd_rn(__fadd_rn(__fmul_rn(hx, hx), __fmul_rn(hy, hy)), __fmul_rn(hz, hz));
        rth[t] = __fadd_rn(__fsqrt_rn(s), 2.4f);
    }
    __syncthreads();
    int i = blk * 256 + t;
    const float* pp = points + (size_t)i * 5;
    float px = pp[0], py = pp[1], pz = pp[2];
    float best = 3.402823466e38f; int bi = 0;
    #pragma unroll 4
    for (int r = 0; r < Rr; r++) {
        float dx = __fsub_rn(px, rcx[r]);
        float dy = __fsub_rn(py, rcy[r]);
        float dz = __fsub_rn(pz, rcz[r]);
        float d2 = __fadd_rn(__fadd_rn(__fmul_rn(dx, dx), __fmul_rn(dy, dy)), __fmul_rn(dz, dz));
        if (d2 < best) { best = d2; bi = r; }     // strict < : first-index tie-break (argmin)
    }
    g_flag[i] = (__fsqrt_rn(best) < rth[bi]) ? 1 : 0;
}

// ---------------- order-preserving compaction: single block-scan pass ----------------
__global__ void compact_kernel(const float* __restrict__ points) {
    int b = blockIdx.x, t = threadIdx.x;           // 2 blocks x 1024
    const int PT = Nn / 1024;                      // 16 consecutive elements/thread
    int lane = t & 31, w = t >> 5;
    int base = b * Nn + t * PT;
    unsigned fl = 0; int c = 0;
    #pragma unroll
    for (int i = 0; i < PT; i++) {
        int fi = g_flag[base + i];
        fl |= (unsigned)fi << i;
        c += fi;
    }
    int inc = c;
    #pragma unroll
    for (int off = 1; off < 32; off <<= 1) {
        int v = __shfl_up_sync(0xffffffffu, inc, off);
        if (lane >= off) inc += v;
    }
    __shared__ int wsum[32], wpre[32], s_total;
    if (lane == 31) wsum[w] = inc;
    __syncthreads();
    if (t < 32) {
        int v = wsum[t], iv = v;
        #pragma unroll
        for (int off = 1; off < 32; off <<= 1) {
            int u = __shfl_up_sync(0xffffffffu, iv, off);
            if (t >= off) iv += u;
        }
        wpre[t] = iv - v;
        if (t == 31) s_total = iv;
    }
    __syncthreads();
    int pos = b * Nn + wpre[w] + (inc - c);
    #pragma unroll
    for (int i = 0; i < PT; i++) {
        if ((fl >> i) & 1u) {
            int src = base + i;
            const float* pp = points + (size_t)src * 5;
            g_cx[pos] = pp[0]; g_cy[pos] = pp[1]; g_cz[pos] = pp[2];
            pos++;
        }
    }
    if (t == 0) {
        int tot = s_total;
        if (tot == 0) {
            const float* pp = points + (size_t)(b * Nn) * 5;
            g_cx[b * Nn] = pp[0]; g_cy[b * Nn] = pp[1]; g_cz[b * Nn] = pp[2];
            tot = 1;
        }
        g_vcount[b] = tot;
    }
}

// ---------------- mid: Morton sort (blocks 0-1) + prep_raw + prep_c3, one launch -----
// The three parts are mutually independent; fusing them overlaps the 2-block sort with
// the wide prep work instead of serializing three launches.
#define MIDT 512
#define RAW_BLKS ((Bb*Nn*32)/MIDT)                 // 2048
#define C3_BLKS  ((Bb*Mm*64)/MIDT)                 // 2048
__global__ void mid_kernel(const float* __restrict__ points,
                           const float* __restrict__ conv3,
                           const float* __restrict__ W_raw, const float* __restrict__ b_raw,
                           const float* __restrict__ W_c3,  const float* __restrict__ b_c3) {
    __shared__ int cnt[4096];
    __shared__ int offs[4096];
    __shared__ int wsc[16];
    int blk = blockIdx.x, t = threadIdx.x;
    if (blk < 2) {
        // ---- Morton-bucket counting sort, 64x64 grid (intra-bucket order is atomic-
        // nondeterministic, but FPS is invariant: d updates are order-independent and
        // argmax tie-breaks carry original compacted rank) ----
        int b = blk;
        int V = g_vcount[b];
        for (int i = t; i < 4096; i += MIDT) cnt[i] = 0;
        __syncthreads();
        for (int i = t; i < V; i += MIDT) {
            float x = g_cx[b*Nn + i], y = g_cy[b*Nn + i];
            int ix = min(63, max(0, (int)((x + 75.2f) * (64.0f / 150.4f))));
            int iy = min(63, max(0, (int)((y + 75.2f) * (64.0f / 150.4f))));
            int code = (int)(p1b1((unsigned)ix) | (p1b1((unsigned)iy) << 1));  // 0..4095
            g_bkt[b*Nn + i] = code;
            atomicAdd(&cnt[code], 1);
        }
        __syncthreads();
        int c8[8]; int v = 0;
        #pragma unroll
        for (int j = 0; j < 8; j++) { c8[j] = cnt[8*t + j]; v += c8[j]; }
        int inc = v;
        int lane = t & 31, w = t >> 5;
        #pragma unroll
        for (int off = 1; off < 32; off <<= 1) {
            int u = __shfl_up_sync(0xffffffffu, inc, off);
            if (lane >= off) inc += u;
        }
        if (lane == 31) wsc[w] = inc;
        __syncthreads();
        if (t < 32) {
            int vv = (t < 16) ? wsc[t] : 0;
            int iv = vv;
            #pragma unroll
            for (int off = 1; off < 16; off <<= 1) {
                int u = __shfl_up_sync(0xffffffffu, iv, off);
                if (t >= off) iv += u;
            }
            if (t < 16) wsc[t] = iv - vv;
        }
        __syncthreads();
        int basep = wsc[w] + (inc - v);
        #pragma unroll
        for (int j = 0; j < 8; j++) { offs[8*t + j] = basep; basep += c8[j]; }
        __syncthreads();
        for (int i = t; i < V; i += MIDT) {
            int code = g_bkt[b*Nn + i];
            int pos = atomicAdd(&offs[code], 1);
            g_sx[b*Nn + pos] = g_cx[b*Nn + i];
            g_sy[b*Nn + pos] = g_cy[b*Nn + i];
            g_sz[b*Nn + pos] = g_cz[b*Nn + i];
            g_srank[b*Nn + pos] = i;
        }
    } else if (blk < 2 + RAW_BLKS) {
        // ---- prep_raw: point SoA + relu(pf @ W_raw + b) ----
        int gid = (blk - 2) * MIDT + t;
        int p = gid >> 5, c = gid & 31;
        const float* pp = points + (size_t)p * 5;
        float v = fmaxf(pp[3] * W_raw[c] + pp[4] * W_raw[32 + c] + b_raw[c], 0.0f);
        g_fraw[(size_t)p * 32 + c] = v;
        if (c < 3) {
            float cv = pp[c];
            if (c == 0) g_px[p] = cv; else if (c == 1) g_py[p] = cv; else g_pz[p] = cv;
        }
    } else {
        // ---- prep_c3: conv3 SoA + relu(cf @ W_c3 + b) ----
        int gid = (blk - 2 - RAW_BLKS) * MIDT + t;
        int p = gid >> 6, c = gid & 63;
        const float* fp = conv3 + (size_t)p * 67;
        float acc = 0.0f;
        #pragma unroll 8
        for (int k = 0; k < 64; k++) acc = fmaf(fp[3 + k], W_c3[k * 64 + c], acc);
        acc = fmaxf(acc + b_c3[c], 0.0f);
        g_fc3[(size_t)p * 64 + c] = acc;
        if (c < 3) {
            float cv = fp[c];
            if (c == 0) g_qx[p] = cv; else if (c == 1) g_qy[p] = cv; else g_qz[p] = cv;
        }
    }
}

// ---------------- FPS v8: REG_P=12 (RCOV=6144 >= V), bbox prune, warp caching --------
#define FPS_T 512
#define REG_P 12
__global__ void __launch_bounds__(FPS_T, 1) fps_kernel(float* __restrict__ out) {
    int b = blockIdx.x, t = threadIdx.x;
    extern __shared__ float sm[];
    float2* sxy = reinterpret_cast<float2*>(sm);   // [Nn] coords in ORIGINAL rank order
    float*  szz = sm + 2 * Nn;                     // [Nn]
    __shared__ unsigned red_v[2][16], red_i[2][16];
    int V = g_vcount[b];

    for (int i = t; i < V; i += FPS_T) {
        sxy[i] = make_float2(g_cx[b*Nn + i], g_cy[b*Nn + i]);
        szz[i] = g_cz[b*Nn + i];
    }
    int base = t * REG_P;
    unsigned long long rx[REG_P/2], ry[REG_P/2], rz[REG_P/2];
    float d[REG_P];
    unsigned rnk[REG_P];
    float mnx = 3e38f, mxx = -3e38f, mny = 3e38f, mxy = -3e38f, mnz = 3e38f, mxz = -3e38f;
    #pragma unroll
    for (int p = 0; p < REG_P/2; p++) {
        float x0 = 0.f, y0 = 0.f, z0 = 0.f, x1 = 0.f, y1 = 0.f, z1 = 0.f;
        int c0 = base + 2*p, c1 = base + 2*p + 1;
        if (c0 < V) {
            x0 = g_sx[b*Nn + c0]; y0 = g_sy[b*Nn + c0]; z0 = g_sz[b*Nn + c0];
            rnk[2*p] = (unsigned)g_srank[b*Nn + c0]; d[2*p] = 1e10f;
            mnx = fminf(mnx, x0); mxx = fmaxf(mxx, x0);
            mny = fminf(mny, y0); mxy = fmaxf(mxy, y0);
            mnz = fminf(mnz, z0); mxz = fmaxf(mxz, z0);
        } else { rnk[2*p] = 0xffffffffu; d[2*p] = -3.0e38f; }
        if (c1 < V) {
            x1 = g_sx[b*Nn + c1]; y1 = g_sy[b*Nn + c1]; z1 = g_sz[b*Nn + c1];
            rnk[2*p+1] = (unsigned)g_srank[b*Nn + c1]; d[2*p+1] = 1e10f;
            mnx = fminf(mnx, x1); mxx = fmaxf(mxx, x1);
            mny = fminf(mny, y1); mxy = fmaxf(mxy, y1);
            mnz = fminf(mnz, z1); mxz = fmaxf(mxz, z1);
        } else { rnk[2*p+1] = 0xffffffffu; d[2*p+1] = -3.0e38f; }
        rx[p] = pk2(x0, x1); ry[p] = pk2(y0, y1); rz[p] = pk2(z0, z1);
    }
    bool active = (base < V);
    float bv = -3.4e38f;
    #pragma unroll
    for (int j = 0; j < REG_P; j++) bv = fmaxf(bv, d[j]);
    unsigned besti = 0xffffffffu;
    #pragma unroll
    for (int j = 0; j < REG_P; j++) if (d[j] == bv) besti = min(besti, rnk[j]);
    const int RCOV = REG_P * FPS_T;                // 6144 >= any plausible V (~5000)
    bool ovf = (V > RCOV);
    float bvo = -3.4e38f; unsigned bio = 0xffffffffu;
    if (ovf) {
        for (int i = RCOV + t; i < V; i += FPS_T) {
            g_dov[b*Nn + i] = 1e10f;
            bvo = 1e10f;
            bio = min(bio, (unsigned)g_srank[b*Nn + i]);
        }
    }
    int lane = t & 31, widx = t >> 5;
    bool upd = true;                               // force full reduce on iteration 0
    unsigned cache_m = 0, cache_wbi = 0xffffffffu;
    __syncthreads();

    for (int k = 0; k < Kk; k++) {
        // ---- L1 reduce, skipped when the whole warp is unchanged ----
        float cbv = bv; unsigned cbi = besti;
        if (ovf) {
            if (bvo > cbv) { cbv = bvo; cbi = bio; }
            else if (bvo == cbv) cbi = min(cbi, bio);
            upd = true;
        }
        unsigned ub = __ballot_sync(0xffffffffu, upd);
        unsigned m, wbi;
        if (ub) {
            unsigned vb = (cbi != 0xffffffffu) ? __float_as_uint(cbv) : 0u;
            m = __reduce_max_sync(0xffffffffu, vb);
            unsigned cand = (vb == m && cbi != 0xffffffffu) ? cbi : 0xffffffffu;
            wbi = __reduce_min_sync(0xffffffffu, cand);
            cache_m = m; cache_wbi = wbi;
        } else {
            m = cache_m; wbi = cache_wbi;
        }
        int par = k & 1;
        if (lane == 0) { red_v[par][widx] = m; red_i[par][widx] = wbi; }
        __syncthreads();
        // ---- L2: 16 warp results, reduced redundantly by every warp ----
        unsigned v2 = (lane < 16) ? red_v[par][lane] : 0u;
        unsigned i2 = (lane < 16) ? red_i[par][lane] : 0xffffffffu;
        unsigned gm = __reduce_max_sync(0xffffffffu, v2);
        unsigned c2 = (v2 == gm) ? i2 : 0xffffffffu;
        unsigned gbi = __reduce_min_sync(0xffffffffu, c2);
        float2 xy = sxy[gbi];
        float bx = xy.x, by = xy.y, bz = szz[gbi];
        if (t == (k & (FPS_T - 1))) {              // distributed winner store (gmem only;
            int row = b * Kk + k;                  //  d_out copy happens in post_kernel)
            g_kpx[row] = bx; g_kpy[row] = by; g_kpz[row] = bz;
        }
        if (k + 1 == Kk) break;
        // ---- pruned update ----
        upd = false;
        if (active) {
            float dxl = fmaxf(fmaxf(mnx - bx, bx - mxx), 0.0f);
            float dyl = fmaxf(fmaxf(mny - by, by - mxy), 0.0f);
            float dzl = fmaxf(fmaxf(mnz - bz, bz - mxz), 0.0f);
            float lb = dxl*dxl + dyl*dyl + dzl*dzl;
            if (lb * 0.99999f < bv) {              // margin covers fp32 rounding slack
                upd = true;
                unsigned long long nbx = pk2(-bx, -bx), nby = pk2(-by, -by), nbz = pk2(-bz, -bz);
                #pragma unroll
                for (int p = 0; p < REG_P/2; p++) {
                    unsigned long long dx = add2(rx[p], nbx);
                    unsigned long long dy = add2(ry[p], nby);
                    unsigned long long dz = add2(rz[p], nbz);
                    unsigned long long s  = add2(add2(mul2(dx,dx), mul2(dy,dy)), mul2(dz,dz));
                    float s0, s1; upk2(s, s0, s1);
                    d[2*p]   = fminf(d[2*p],   s0);
                    d[2*p+1] = fminf(d[2*p+1], s1);
                }
                bv = -3.4e38f;
                #pragma unroll
                for (int j = 0; j < REG_P; j++) bv = fmaxf(bv, d[j]);
                besti = 0xffffffffu;
                #pragma unroll
                for (int j = 0; j < REG_P; j++) if (d[j] == bv) besti = min(besti, rnk[j]);
            }
        }
        if (ovf) {                                 // dead for V <= 6144 (safety only)
            bvo = -3.4e38f; bio = 0xffffffffu;
            for (int ci = RCOV + t; ci < V; ci += FPS_T) {
                float sxv = g_sx[b*Nn + ci], syv = g_sy[b*Nn + ci], szv = g_sz[b*Nn + ci];
                float dx = __fsub_rn(sxv, bx);
                float dy = __fsub_rn(syv, by);
                float dz = __fsub_rn(szv, bz);
                float nd = __fadd_rn(__fadd_rn(__fmul_rn(dx,dx), __fmul_rn(dy,dy)),
                                     __fmul_rn(dz,dz));
                float nv = fminf(g_dov[b*Nn + ci], nd);
                g_dov[b*Nn + ci] = nv;
                unsigned rr = (unsigned)g_srank[b*Nn + ci];
                if (nv > bvo) { bvo = nv; bio = rr; }
                else if (nv == bvo) bio = min(bio, rr);
            }
        }
    }
}

// ---------------- post: c3_agg + raw_agg + bev (+ keypoint copy), one launch ---------
// All three depend only on keypoints + their prep outputs and write disjoint g_feats
// columns; fusing overlaps them across the idle chip. Long-running c3_agg goes first.
__global__ void post_kernel(const float* __restrict__ spatial, float* __restrict__ out) {
    int blk = blockIdx.x, t = threadIdx.x;         // 256 threads
    if (blk < 512) {
        // ---- conv3 radius aggregation (r=1.6, 64 feats) ----
        int b = blk / (Kk / 8);
        int g = blk % (Kk / 8);
        __shared__ float kx[8], ky[8], kz[8];
        __shared__ float acc[8][65];
        if (t < 8) {
            int row = b * Kk + g * 8 + t;
            kx[t] = g_kpx[row]; ky[t] = g_kpy[row]; kz[t] = g_kpz[row];
        }
        for (int idx = t; idx < 8 * 65; idx += 256) ((float*)acc)[idx] = 0.0f;
        __syncthreads();
        for (int i = t; i < Mm; i += 256) {
            float px = g_qx[b * Mm + i], py = g_qy[b * Mm + i], pz = g_qz[b * Mm + i];
            const float* f = g_fc3 + (size_t)(b * Mm + i) * 64;
            #pragma unroll
            for (int q = 0; q < 8; q++) {
                float dx = px - kx[q], dy = py - ky[q], dz = pz - kz[q];
                float d2 = fmaf(dx, dx, fmaf(dy, dy, dz * dz));
                if (d2 < 2.56f) {
                    #pragma unroll
                    for (int c = 0; c < 64; c++) atomicAdd(&acc[q][c], f[c]);
                    atomicAdd(&acc[q][64], 1.0f);
                }
            }
        }
        __syncthreads();
        for (int idx = t; idx < 8 * 64; idx += 256) {
            int q = idx >> 6, c = idx & 63;
            float cnt = fmaxf(acc[q][64], 1.0f);
            g_feats[(size_t)(b * Kk + g * 8 + q) * 352 + 288 + c] = acc[q][c] / cnt;
        }
    } else if (blk < 1024) {
        // ---- raw-point radius aggregation (r=0.8, 32 feats) ----
        int bb = blk - 512;
        int b = bb / (Kk / 8);
        int g = bb % (Kk / 8);
        __shared__ float kx2[8], ky2[8], kz2[8];
        __shared__ float acc2[8][33];
        if (t < 8) {
            int row = b * Kk + g * 8 + t;
            kx2[t] = g_kpx[row]; ky2[t] = g_kpy[row]; kz2[t] = g_kpz[row];
        }
        for (int idx = t; idx < 8 * 33; idx += 256) ((float*)acc2)[idx] = 0.0f;
        __syncthreads();
        for (int i = t; i < Nn; i += 256) {
            float px = g_px[b * Nn + i], py = g_py[b * Nn + i], pz = g_pz[b * Nn + i];
            const float* f = g_fraw + (size_t)(b * Nn + i) * 32;
            #pragma unroll
            for (int q = 0; q < 8; q++) {
                float dx = px - kx2[q], dy = py - ky2[q], dz = pz - kz2[q];
                float d2 = fmaf(dx, dx, fmaf(dy, dy, dz * dz));
                if (d2 < 0.64f) {
                    #pragma unroll
                    for (int c = 0; c < 32; c++) atomicAdd(&acc2[q][c], f[c]);
                    atomicAdd(&acc2[q][32], 1.0f);
                }
            }
        }
        __syncthreads();
        int q = t >> 5, c = t & 31;
        float cnt = fmaxf(acc2[q][32], 1.0f);
        g_feats[(size_t)(b * Kk + g * 8 + q) * 352 + 256 + c] = acc2[q][c] / cnt;
    } else {
        // ---- BEV bilinear gather + keypoint copy into d_out ----
        int idx = blk - 1024;                      // 0..4095
        int kpi = idx & (Kk - 1), b = idx >> 11;
        int row = b * Kk + kpi;
        float kx = g_kpx[row], ky = g_kpy[row];
        if (t < 3) {                               // keypoints -> d_out tail section
            float* outkp = out + (size_t)Bb * Kk * 128;
            float v = (t == 0) ? kx : (t == 1) ? ky : g_kpz[row];
            outkp[(size_t)row * 3 + t] = v;
        }
        int c = t;                                 // 256 channels
        float x = ((kx - (-75.2f)) / 0.1f) / 8.0f;
        float y = ((ky - (-75.2f)) / 0.1f) / 8.0f;
        int x0 = (int)floorf(x); x0 = min(max(x0, 0), 187); int x1 = min(x0 + 1, 187);
        int y0 = (int)floorf(y); y0 = min(max(y0, 0), 187); int y1 = min(y0 + 1, 187);
        float xf0 = (float)x0, xf1 = (float)x1, yf0 = (float)y0, yf1 = (float)y1;
        float wa = (xf1 - x) * (yf1 - y);
        float wb2 = (xf1 - x) * (y - yf0);
        float wc2 = (x - xf0) * (yf1 - y);
        float wd = (x - xf0) * (y - yf0);
        const float* im = spatial + ((size_t)b * 256 + c) * 35344;
        float v = im[y0 * 188 + x0] * wa + im[y1 * 188 + x0] * wb2
                + im[y0 * 188 + x1] * wc2 + im[y1 * 188 + x1] * wd;
        g_feats[(size_t)row * 352 + c] = v;
    }
}

// ---------------- fuse GEMM (4096x352 @ 352x128) + BN + ReLU -------------------------
__global__ void fuse_kernel(const float* __restrict__ Wf,
                            const float* __restrict__ bn_g, const float* __restrict__ bn_b,
                            const float* __restrict__ bn_m, const float* __restrict__ bn_v,
                            float* __restrict__ out) {
    int blk = blockIdx.x;                          // 256 blocks x 16 rows
    int t = threadIdx.x;                           // 128 = output channels
    __shared__ float sf[16 * 352];
    int row0 = blk * 16;
    for (int idx = t; idx < 16 * 352; idx += 128)
        sf[idx] = g_feats[(size_t)row0 * 352 + idx];
    __syncthreads();
    float acc[16];
    #pragma unroll
    for (int r = 0; r < 16; r++) acc[r] = 0.0f;
    for (int k = 0; k < 352; k++) {
        float w = Wf[k * 128 + t];
        #pragma unroll
        for (int r = 0; r < 16; r++) acc[r] = fmaf(sf[r * 352 + k], w, acc[r]);
    }
    float sc = rsqrtf(bn_v[t] + 1e-5f) * bn_g[t];
    float mu = bn_m[t], be = bn_b[t];
    #pragma unroll
    for (int r = 0; r < 16; r++) {
        float v = (acc[r] - mu) * sc + be;
        out[(size_t)(row0 + r) * 128 + t] = fmaxf(v, 0.0f);
    }
}

// ---------------- launch (fps at #4 for the ncu -s5 -c1 capture window) --------------
extern "C" void kernel_launch(void* const* d_in, const int* in_sizes, int n_in,
                              void* d_out, int out_size) {
    const float* points  = (const float*)d_in[0];
    const float* bboxes  = (const float*)d_in[1];
    const float* spatial = (const float*)d_in[2];
    const float* conv3   = (const float*)d_in[3];
    const float* W_raw   = (const float*)d_in[4];
    const float* b_raw   = (const float*)d_in[5];
    const float* W_c3    = (const float*)d_in[6];
    const float* b_c3    = (const float*)d_in[7];
    const float* W_fuse  = (const float*)d_in[8];
    const float* bn_g    = (const float*)d_in[9];
    const float* bn_b    = (const float*)d_in[10];
    const float* bn_m    = (const float*)d_in[11];
    const float* bn_v    = (const float*)d_in[12];
    float* out = (float*)d_out;

    roi_mask_kernel<<<(Bb * Nn) / 256, 256>>>(points, bboxes);               // #1
    compact_kernel<<<Bb, 1024>>>(points);                                    // #2
    mid_kernel<<<2 + RAW_BLKS + C3_BLKS, MIDT>>>(points, conv3,              // #3
                                                 W_raw, b_raw, W_c3, b_c3);

    static const size_t fps_smem = (size_t)3 * Nn * sizeof(float);           // 196608 B
    cudaFuncSetAttribute(fps_kernel, cudaFuncAttributeMaxDynamicSharedMemorySize,
                         (int)fps_smem);
    fps_kernel<<<Bb, FPS_T, fps_smem>>>(out);                                // #4 <- profiled

    post_kernel<<<1024 + Bb * Kk, 256>>>(spatial, out);                      // #5
    fuse_kernel<<<(Bb * Kk) / 16, 128>>>(W_fuse, bn_g, bn_b, bn_m, bn_v, out);  // #6
}

// round 14
// speedup vs baseline: 1.6146x; 1.6146x over previous
#include <cuda_runtime.h>

#define Bb 2
#define Nn 16384
#define Mm 8192
#define Kk 2048
#define Rr 128

// ---------------- scratch (__device__ globals; no allocation allowed) ----------------
__device__ float g_px[Bb*Nn], g_py[Bb*Nn], g_pz[Bb*Nn];
__device__ float g_qx[Bb*Mm], g_qy[Bb*Mm], g_qz[Bb*Mm];
__device__ float g_fraw[Bb*Nn*32];
__device__ float g_fc3[Bb*Mm*64];
__device__ int   g_flag[Bb*Nn];
__device__ float g_cx[Bb*Nn], g_cy[Bb*Nn], g_cz[Bb*Nn];
__device__ int   g_vcount[Bb];
__device__ float g_kpx[Bb*Kk], g_kpy[Bb*Kk], g_kpz[Bb*Kk];
__device__ float g_feats[Bb*Kk*352];
__device__ float g_dov[Bb*Nn];                    // overflow distances (V > RCOV only)
__device__ int   g_bkt[Bb*Nn];                    // Morton bucket per point
__device__ float g_sx[Bb*Nn], g_sy[Bb*Nn], g_sz[Bb*Nn];  // spatially sorted coords
__device__ int   g_srank[Bb*Nn];                  // sorted pos -> original compacted rank

// packed f32x2 helpers (per-lane IEEE rn -> bitwise identical to scalar __fadd_rn/__fmul_rn)
__device__ __forceinline__ unsigned long long pk2(float lo, float hi) {
    unsigned long long r;
    asm("mov.b64 %0, {%1, %2};" : "=l"(r) : "f"(lo), "f"(hi));
    return r;
}
__device__ __forceinline__ void upk2(unsigned long long v, float& lo, float& hi) {
    asm("mov.b64 {%0, %1}, %2;" : "=f"(lo), "=f"(hi) : "l"(v));
}
__device__ __forceinline__ unsigned long long add2(unsigned long long a, unsigned long long b) {
    unsigned long long r;
    asm("add.rn.f32x2 %0, %1, %2;" : "=l"(r) : "l"(a), "l"(b));
    return r;
}
__device__ __forceinline__ unsigned long long mul2(unsigned long long a, unsigned long long b) {
    unsigned long long r;
    asm("mul.rn.f32x2 %0, %1, %2;" : "=l"(r) : "l"(a), "l"(b));
    return r;
}
__device__ __forceinline__ unsigned p1b1(unsigned x) {   // interleave bits with zeros
    x &= 0x0000ffffu;
    x = (x | (x << 8)) & 0x00FF00FFu;
    x = (x | (x << 4)) & 0x0F0F0F0Fu;
    x = (x | (x << 2)) & 0x33333333u;
    x = (x | (x << 1)) & 0x55555555u;
    return x;
}

// ---------------- prep: point SoA + raw point features relu(pf @ W_raw + b) ----------
__global__ void prep_raw_kernel(const float* __restrict__ points,
                                const float* __restrict__ W,
                                const float* __restrict__ bias) {
    int gid = blockIdx.x * 256 + threadIdx.x;      // Bb*Nn*32 threads
    int p = gid >> 5, c = gid & 31;
    const float* pp = points + (size_t)p * 5;
    float v = fmaxf(pp[3] * W[c] + pp[4] * W[32 + c] + bias[c], 0.0f);
    g_fraw[(size_t)p * 32 + c] = v;
    if (c < 3) {
        float cv = pp[c];
        if (c == 0) g_px[p] = cv; else if (c == 1) g_py[p] = cv; else g_pz[p] = cv;
    }
}

// ---------------- prep: conv3 SoA + relu(cf @ W_c3 + b) ------------------------------
__global__ void prep_c3_kernel(const float* __restrict__ conv3,
                               const float* __restrict__ W,
                               const float* __restrict__ bias) {
    int gid = blockIdx.x * 256 + threadIdx.x;      // Bb*Mm*64 threads
    int p = gid >> 6, c = gid & 63;
    const float* fp = conv3 + (size_t)p * 67;
    float acc = 0.0f;
    #pragma unroll 8
    for (int k = 0; k < 64; k++) acc = fmaf(fp[3 + k], W[k * 64 + c], acc);
    acc = fmaxf(acc + bias[c], 0.0f);
    g_fc3[(size_t)p * 64 + c] = acc;
    if (c < 3) {
        float cv = fp[c];
        if (c == 0) g_qx[p] = cv; else if (c == 1) g_qy[p] = cv; else g_qz[p] = cv;
    }
}

// ---------------- ROI validity mask (bitwise-strict fp32, no contraction) ------------
__global__ void roi_mask_kernel(const float* __restrict__ points,
                                const float* __restrict__ bboxes) {
    int blk = blockIdx.x;                          // Bb*Nn/256 blocks, batch-aligned
    int b = blk / (Nn / 256);
    int t = threadIdx.x;
    __shared__ float rcx[Rr], rcy[Rr], rcz[Rr], rth[Rr];
    if (t < Rr) {
        const float* bb = bboxes + ((size_t)b * Rr + t) * 7;
        rcx[t] = bb[0]; rcy[t] = bb[1]; rcz[t] = bb[2];
        float hx = __fmul_rn(bb[3], 0.5f);
        float hy = __fmul_rn(bb[4], 0.5f);
        float hz = __fmul_rn(bb[5], 0.5f);
        float s = __fadd_rn(__fadd_rn(__fmul_rn(hx, hx), __fmul_rn(hy, hy)), __fmul_rn(hz, hz));
        rth[t] = __fadd_rn(__fsqrt_rn(s), 2.4f);
    }
    __syncthreads();
    int i = blk * 256 + t;
    const float* pp = points + (size_t)i * 5;
    float px = pp[0], py = pp[1], pz = pp[2];
    float best = 3.402823466e38f; int bi = 0;
    #pragma unroll 4
    for (int r = 0; r < Rr; r++) {
        float dx = __fsub_rn(px, rcx[r]);
        float dy = __fsub_rn(py, rcy[r]);
        float dz = __fsub_rn(pz, rcz[r]);
        float d2 = __fadd_rn(__fadd_rn(__fmul_rn(dx, dx), __fmul_rn(dy, dy)), __fmul_rn(dz, dz));
        if (d2 < best) { best = d2; bi = r; }     // strict < : first-index tie-break (argmin)
    }
    g_flag[i] = (__fsqrt_rn(best) < rth[bi]) ? 1 : 0;
}

// ---------------- order-preserving compaction: single block-scan pass ----------------
__global__ void compact_kernel(const float* __restrict__ points) {
    int b = blockIdx.x, t = threadIdx.x;           // 2 blocks x 1024
    const int PT = Nn / 1024;                      // 16 consecutive elements/thread
    int lane = t & 31, w = t >> 5;
    int base = b * Nn + t * PT;
    unsigned fl = 0; int c = 0;
    #pragma unroll
    for (int i = 0; i < PT; i++) {
        int fi = g_flag[base + i];
        fl |= (unsigned)fi << i;
        c += fi;
    }
    int inc = c;
    #pragma unroll
    for (int off = 1; off < 32; off <<= 1) {
        int v = __shfl_up_sync(0xffffffffu, inc, off);
        if (lane >= off) inc += v;
    }
    __shared__ int wsum[32], wpre[32], s_total;
    if (lane == 31) wsum[w] = inc;
    __syncthreads();
    if (t < 32) {
        int v = wsum[t], iv = v;
        #pragma unroll
        for (int off = 1; off < 32; off <<= 1) {
            int u = __shfl_up_sync(0xffffffffu, iv, off);
            if (t >= off) iv += u;
        }
        wpre[t] = iv - v;
        if (t == 31) s_total = iv;
    }
    __syncthreads();
    int pos = b * Nn + wpre[w] + (inc - c);
    #pragma unroll
    for (int i = 0; i < PT; i++) {
        if ((fl >> i) & 1u) {
            int src = base + i;
            const float* pp = points + (size_t)src * 5;
            g_cx[pos] = pp[0]; g_cy[pos] = pp[1]; g_cz[pos] = pp[2];
            pos++;
        }
    }
    if (t == 0) {
        int tot = s_total;
        if (tot == 0) {
            const float* pp = points + (size_t)(b * Nn) * 5;
            g_cx[b * Nn] = pp[0]; g_cy[b * Nn] = pp[1]; g_cz[b * Nn] = pp[2];
            tot = 1;
        }
        g_vcount[b] = tot;
    }
}

// ---------------- Morton-bucket counting sort, 64x64 grid (tighter FPS bboxes) -------
__global__ void sort_kernel() {
    int b = blockIdx.x, t = threadIdx.x;           // 2 blocks x 512
    __shared__ int cnt[4096];
    __shared__ int offs[4096];
    __shared__ int wsc[16];
    int V = g_vcount[b];
    for (int i = t; i < 4096; i += 512) cnt[i] = 0;
    __syncthreads();
    for (int i = t; i < V; i += 512) {
        float x = g_cx[b*Nn + i], y = g_cy[b*Nn + i];
        int ix = min(63, max(0, (int)((x + 75.2f) * (64.0f / 150.4f))));
        int iy = min(63, max(0, (int)((y + 75.2f) * (64.0f / 150.4f))));
        int code = (int)(p1b1((unsigned)ix) | (p1b1((unsigned)iy) << 1));   // 0..4095
        g_bkt[b*Nn + i] = code;
        atomicAdd(&cnt[code], 1);
    }
    __syncthreads();
    int c8[8]; int v = 0;
    #pragma unroll
    for (int j = 0; j < 8; j++) { c8[j] = cnt[8*t + j]; v += c8[j]; }
    int inc = v;
    int lane = t & 31, w = t >> 5;
    #pragma unroll
    for (int off = 1; off < 32; off <<= 1) {
        int u = __shfl_up_sync(0xffffffffu, inc, off);
        if (lane >= off) inc += u;
    }
    if (lane == 31) wsc[w] = inc;
    __syncthreads();
    if (t < 32) {
        int vv = (t < 16) ? wsc[t] : 0;
        int iv = vv;
        #pragma unroll
        for (int off = 1; off < 16; off <<= 1) {
            int u = __shfl_up_sync(0xffffffffu, iv, off);
            if (t >= off) iv += u;
        }
        if (t < 16) wsc[t] = iv - vv;
    }
    __syncthreads();
    int basep = wsc[w] + (inc - v);
    #pragma unroll
    for (int j = 0; j < 8; j++) { offs[8*t + j] = basep; basep += c8[j]; }
    __syncthreads();
    for (int i = t; i < V; i += 512) {
        int code = g_bkt[b*Nn + i];
        int pos = atomicAdd(&offs[code], 1);
        g_sx[b*Nn + pos] = g_cx[b*Nn + i];
        g_sy[b*Nn + pos] = g_cy[b*Nn + i];
        g_sz[b*Nn + pos] = g_cz[b*Nn + i];
        g_srank[b*Nn + pos] = i;
    }
}

// ---------------- FPS v8 (R12 verbatim): REG_P=12, bbox prune, warp caching ----------
#define FPS_T 512
#define REG_P 12
__global__ void __launch_bounds__(FPS_T, 1) fps_kernel(float* __restrict__ out) {
    int b = blockIdx.x, t = threadIdx.x;
    extern __shared__ float sm[];
    float2* sxy = reinterpret_cast<float2*>(sm);   // [Nn] coords in ORIGINAL rank order
    float*  szz = sm + 2 * Nn;                     // [Nn]
    __shared__ unsigned red_v[2][16], red_i[2][16];
    int V = g_vcount[b];

    for (int i = t; i < V; i += FPS_T) {
        sxy[i] = make_float2(g_cx[b*Nn + i], g_cy[b*Nn + i]);
        szz[i] = g_cz[b*Nn + i];
    }
    int base = t * REG_P;
    unsigned long long rx[REG_P/2], ry[REG_P/2], rz[REG_P/2];
    float d[REG_P];
    unsigned rnk[REG_P];
    float mnx = 3e38f, mxx = -3e38f, mny = 3e38f, mxy = -3e38f, mnz = 3e38f, mxz = -3e38f;
    #pragma unroll
    for (int p = 0; p < REG_P/2; p++) {
        float x0 = 0.f, y0 = 0.f, z0 = 0.f, x1 = 0.f, y1 = 0.f, z1 = 0.f;
        int c0 = base + 2*p, c1 = base + 2*p + 1;
        if (c0 < V) {
            x0 = g_sx[b*Nn + c0]; y0 = g_sy[b*Nn + c0]; z0 = g_sz[b*Nn + c0];
            rnk[2*p] = (unsigned)g_srank[b*Nn + c0]; d[2*p] = 1e10f;
            mnx = fminf(mnx, x0); mxx = fmaxf(mxx, x0);
            mny = fminf(mny, y0); mxy = fmaxf(mxy, y0);
            mnz = fminf(mnz, z0); mxz = fmaxf(mxz, z0);
        } else { rnk[2*p] = 0xffffffffu; d[2*p] = -3.0e38f; }
        if (c1 < V) {
            x1 = g_sx[b*Nn + c1]; y1 = g_sy[b*Nn + c1]; z1 = g_sz[b*Nn + c1];
            rnk[2*p+1] = (unsigned)g_srank[b*Nn + c1]; d[2*p+1] = 1e10f;
            mnx = fminf(mnx, x1); mxx = fmaxf(mxx, x1);
            mny = fminf(mny, y1); mxy = fmaxf(mxy, y1);
            mnz = fminf(mnz, z1); mxz = fmaxf(mxz, z1);
        } else { rnk[2*p+1] = 0xffffffffu; d[2*p+1] = -3.0e38f; }
        rx[p] = pk2(x0, x1); ry[p] = pk2(y0, y1); rz[p] = pk2(z0, z1);
    }
    bool active = (base < V);
    float bv = -3.4e38f;
    #pragma unroll
    for (int j = 0; j < REG_P; j++) bv = fmaxf(bv, d[j]);
    unsigned besti = 0xffffffffu;
    #pragma unroll
    for (int j = 0; j < REG_P; j++) if (d[j] == bv) besti = min(besti, rnk[j]);
    const int RCOV = REG_P * FPS_T;                // 6144 >= any plausible V (~5000)
    bool ovf = (V > RCOV);
    float bvo = -3.4e38f; unsigned bio = 0xffffffffu;
    if (ovf) {
        for (int i = RCOV + t; i < V; i += FPS_T) {
            g_dov[b*Nn + i] = 1e10f;
            bvo = 1e10f;
            bio = min(bio, (unsigned)g_srank[b*Nn + i]);
        }
    }
    int lane = t & 31, widx = t >> 5;
    bool upd = true;                               // force full reduce on iteration 0
    unsigned cache_m = 0, cache_wbi = 0xffffffffu;
    __syncthreads();

    float* outkp = out + (size_t)Bb * Kk * 128;    // keypoints section of d_out

    for (int k = 0; k < Kk; k++) {
        // ---- L1 reduce, skipped when the whole warp is unchanged ----
        float cbv = bv; unsigned cbi = besti;
        if (ovf) {
            if (bvo > cbv) { cbv = bvo; cbi = bio; }
            else if (bvo == cbv) cbi = min(cbi, bio);
            upd = true;
        }
        unsigned ub = __ballot_sync(0xffffffffu, upd);
        unsigned m, wbi;
        if (ub) {
            unsigned vb = (cbi != 0xffffffffu) ? __float_as_uint(cbv) : 0u;
            m = __reduce_max_sync(0xffffffffu, vb);
            unsigned cand = (vb == m && cbi != 0xffffffffu) ? cbi : 0xffffffffu;
            wbi = __reduce_min_sync(0xffffffffu, cand);
            cache_m = m; cache_wbi = wbi;
        } else {
            m = cache_m; wbi = cache_wbi;
        }
        int par = k & 1;
        if (lane == 0) { red_v[par][widx] = m; red_i[par][widx] = wbi; }
        __syncthreads();
        // ---- L2: 16 warp results, reduced redundantly by every warp ----
        unsigned v2 = (lane < 16) ? red_v[par][lane] : 0u;
        unsigned i2 = (lane < 16) ? red_i[par][lane] : 0xffffffffu;
        unsigned gm = __reduce_max_sync(0xffffffffu, v2);
        unsigned c2 = (v2 == gm) ? i2 : 0xffffffffu;
        unsigned gbi = __reduce_min_sync(0xffffffffu, c2);
        float2 xy = sxy[gbi];
        float bx = xy.x, by = xy.y, bz = szz[gbi];
        if (t == (k & (FPS_T - 1))) {
            int row = b * Kk + k;
            g_kpx[row] = bx; g_kpy[row] = by; g_kpz[row] = bz;
            outkp[(size_t)row * 3 + 0] = bx;
            outkp[(size_t)row * 3 + 1] = by;
            outkp[(size_t)row * 3 + 2] = bz;
        }
        if (k + 1 == Kk) break;
        // ---- pruned update ----
        upd = false;
        if (active) {
            float dxl = fmaxf(fmaxf(mnx - bx, bx - mxx), 0.0f);
            float dyl = fmaxf(fmaxf(mny - by, by - mxy), 0.0f);
            float dzl = fmaxf(fmaxf(mnz - bz, bz - mxz), 0.0f);
            float lb = dxl*dxl + dyl*dyl + dzl*dzl;
            if (lb * 0.99999f < bv) {              // margin covers fp32 rounding slack
                upd = true;
                unsigned long long nbx = pk2(-bx, -bx), nby = pk2(-by, -by), nbz = pk2(-bz, -bz);
                #pragma unroll
                for (int p = 0; p < REG_P/2; p++) {
                    unsigned long long dx = add2(rx[p], nbx);
                    unsigned long long dy = add2(ry[p], nby);
                    unsigned long long dz = add2(rz[p], nbz);
                    unsigned long long s  = add2(add2(mul2(dx,dx), mul2(dy,dy)), mul2(dz,dz));
                    float s0, s1; upk2(s, s0, s1);
                    d[2*p]   = fminf(d[2*p],   s0);
                    d[2*p+1] = fminf(d[2*p+1], s1);
                }
                bv = -3.4e38f;
                #pragma unroll
                for (int j = 0; j < REG_P; j++) bv = fmaxf(bv, d[j]);
                besti = 0xffffffffu;
                #pragma unroll
                for (int j = 0; j < REG_P; j++) if (d[j] == bv) besti = min(besti, rnk[j]);
            }
        }
        if (ovf) {                                 // dead for V <= 6144 (safety only)
            bvo = -3.4e38f; bio = 0xffffffffu;
            for (int ci = RCOV + t; ci < V; ci += FPS_T) {
                float sxv = g_sx[b*Nn + ci], syv = g_sy[b*Nn + ci], szv = g_sz[b*Nn + ci];
                float dx = __fsub_rn(sxv, bx);
                float dy = __fsub_rn(syv, by);
                float dz = __fsub_rn(szv, bz);
                float nd = __fadd_rn(__fadd_rn(__fmul_rn(dx,dx), __fmul_rn(dy,dy)),
                                     __fmul_rn(dz,dz));
                float nv = fminf(g_dov[b*Nn + ci], nd);
                g_dov[b*Nn + ci] = nv;
                unsigned rr = (unsigned)g_srank[b*Nn + ci];
                if (nv > bvo) { bvo = nv; bio = rr; }
                else if (nv == bvo) bio = min(bio, rr);
            }
        }
    }
}

// ---------------- post: c3_agg + raw_agg + bev, one launch (runs AFTER fps) ----------
// The three are independent given keypoints + prep outputs and write disjoint g_feats
// columns; fusing overlaps them across the chip. Long-running c3_agg blocks first.
__global__ void post_kernel(const float* __restrict__ spatial) {
    int blk = blockIdx.x, t = threadIdx.x;         // 256 threads
    if (blk < 512) {
        // ---- conv3 radius aggregation (r=1.6, 64 feats) ----
        int b = blk / (Kk / 8);
        int g = blk % (Kk / 8);
        __shared__ float kx[8], ky[8], kz[8];
        __shared__ float acc[8][65];
        if (t < 8) {
            int row = b * Kk + g * 8 + t;
            kx[t] = g_kpx[row]; ky[t] = g_kpy[row]; kz[t] = g_kpz[row];
        }
        for (int idx = t; idx < 8 * 65; idx += 256) ((float*)acc)[idx] = 0.0f;
        __syncthreads();
        for (int i = t; i < Mm; i += 256) {
            float px = g_qx[b * Mm + i], py = g_qy[b * Mm + i], pz = g_qz[b * Mm + i];
            const float* f = g_fc3 + (size_t)(b * Mm + i) * 64;
            #pragma unroll
            for (int q = 0; q < 8; q++) {
                float dx = px - kx[q], dy = py - ky[q], dz = pz - kz[q];
                float d2 = fmaf(dx, dx, fmaf(dy, dy, dz * dz));
                if (d2 < 2.56f) {                  // f32(1.6*1.6 in f64) == 2.56f
                    #pragma unroll
                    for (int c = 0; c < 64; c++) atomicAdd(&acc[q][c], f[c]);
                    atomicAdd(&acc[q][64], 1.0f);
                }
            }
        }
        __syncthreads();
        for (int idx = t; idx < 8 * 64; idx += 256) {
            int q = idx >> 6, c = idx & 63;
            float cnt = fmaxf(acc[q][64], 1.0f);
            g_feats[(size_t)(b * Kk + g * 8 + q) * 352 + 288 + c] = acc[q][c] / cnt;
        }
    } else if (blk < 1024) {
        // ---- raw-point radius aggregation (r=0.8, 32 feats) ----
        int bb = blk - 512;
        int b = bb / (Kk / 8);
        int g = bb % (Kk / 8);
        __shared__ float kx2[8], ky2[8], kz2[8];
        __shared__ float acc2[8][33];
        if (t < 8) {
            int row = b * Kk + g * 8 + t;
            kx2[t] = g_kpx[row]; ky2[t] = g_kpy[row]; kz2[t] = g_kpz[row];
        }
        for (int idx = t; idx < 8 * 33; idx += 256) ((float*)acc2)[idx] = 0.0f;
        __syncthreads();
        for (int i = t; i < Nn; i += 256) {
            float px = g_px[b * Nn + i], py = g_py[b * Nn + i], pz = g_pz[b * Nn + i];
            const float* f = g_fraw + (size_t)(b * Nn + i) * 32;
            #pragma unroll
            for (int q = 0; q < 8; q++) {
                float dx = px - kx2[q], dy = py - ky2[q], dz = pz - kz2[q];
                float d2 = fmaf(dx, dx, fmaf(dy, dy, dz * dz));
                if (d2 < 0.64f) {                  // f32(0.8*0.8 in f64) == 0.64f
                    #pragma unroll
                    for (int c = 0; c < 32; c++) atomicAdd(&acc2[q][c], f[c]);
                    atomicAdd(&acc2[q][32], 1.0f);
                }
            }
        }
        __syncthreads();
        int q = t >> 5, c = t & 31;
        float cnt = fmaxf(acc2[q][32], 1.0f);
        g_feats[(size_t)(b * Kk + g * 8 + q) * 352 + 256 + c] = acc2[q][c] / cnt;
    } else {
        // ---- BEV bilinear gather ----
        int idx = blk - 1024;                      // 0..4095
        int kpi = idx & (Kk - 1), b = idx >> 11;
        int row = b * Kk + kpi;
        float kx = g_kpx[row], ky = g_kpy[row];
        int c = t;                                 // 256 channels
        float x = ((kx - (-75.2f)) / 0.1f) / 8.0f;
        float y = ((ky - (-75.2f)) / 0.1f) / 8.0f;
        int x0 = (int)floorf(x); x0 = min(max(x0, 0), 187); int x1 = min(x0 + 1, 187);
        int y0 = (int)floorf(y); y0 = min(max(y0, 0), 187); int y1 = min(y0 + 1, 187);
        float xf0 = (float)x0, xf1 = (float)x1, yf0 = (float)y0, yf1 = (float)y1;
        float wa = (xf1 - x) * (yf1 - y);
        float wb2 = (xf1 - x) * (y - yf0);
        float wc2 = (x - xf0) * (yf1 - y);
        float wd = (x - xf0) * (y - yf0);
        const float* im = spatial + ((size_t)b * 256 + c) * 35344;
        float v = im[y0 * 188 + x0] * wa + im[y1 * 188 + x0] * wb2
                + im[y0 * 188 + x1] * wc2 + im[y1 * 188 + x1] * wd;
        g_feats[(size_t)row * 352 + c] = v;
    }
}

// ---------------- fuse GEMM (4096x352 @ 352x128) + BN + ReLU -------------------------
__global__ void fuse_kernel(const float* __restrict__ Wf,
                            const float* __restrict__ bn_g, const float* __restrict__ bn_b,
                            const float* __restrict__ bn_m, const float* __restrict__ bn_v,
                            float* __restrict__ out) {
    int blk = blockIdx.x;                          // 256 blocks x 16 rows
    int t = threadIdx.x;                           // 128 = output channels
    __shared__ float sf[16 * 352];
    int row0 = blk * 16;
    for (int idx = t; idx < 16 * 352; idx += 128)
        sf[idx] = g_feats[(size_t)row0 * 352 + idx];
    __syncthreads();
    float acc[16];
    #pragma unroll
    for (int r = 0; r < 16; r++) acc[r] = 0.0f;
    for (int k = 0; k < 352; k++) {
        float w = Wf[k * 128 + t];
        #pragma unroll
        for (int r = 0; r < 16; r++) acc[r] = fmaf(sf[r * 352 + k], w, acc[r]);
    }
    float sc = rsqrtf(bn_v[t] + 1e-5f) * bn_g[t];
    float mu = bn_m[t], be = bn_b[t];
    #pragma unroll
    for (int r = 0; r < 16; r++) {
        float v = (acc[r] - mu) * sc + be;
        out[(size_t)(row0 + r) * 128 + t] = fmaxf(v, 0.0f);
    }
}

// ---------------- launch (R12 order; only {bev,raw,c3} -> post_kernel) ---------------
extern "C" void kernel_launch(void* const* d_in, const int* in_sizes, int n_in,
                              void* d_out, int out_size) {
    const float* points  = (const float*)d_in[0];
    const float* bboxes  = (const float*)d_in[1];
    const float* spatial = (const float*)d_in[2];
    const float* conv3   = (const float*)d_in[3];
    const float* W_raw   = (const float*)d_in[4];
    const float* b_raw   = (const float*)d_in[5];
    const float* W_c3    = (const float*)d_in[6];
    const float* b_c3    = (const float*)d_in[7];
    const float* W_fuse  = (const float*)d_in[8];
    const float* bn_g    = (const float*)d_in[9];
    const float* bn_b    = (const float*)d_in[10];
    const float* bn_m    = (const float*)d_in[11];
    const float* bn_v    = (const float*)d_in[12];
    float* out = (float*)d_out;

    roi_mask_kernel<<<(Bb * Nn) / 256, 256>>>(points, bboxes);               // #1
    compact_kernel<<<Bb, 1024>>>(points);                                    // #2
    sort_kernel<<<Bb, 512>>>();                                              // #3

    static const size_t fps_smem = (size_t)3 * Nn * sizeof(float);           // 196608 B
    cudaFuncSetAttribute(fps_kernel, cudaFuncAttributeMaxDynamicSharedMemorySize,
                         (int)fps_smem);
    fps_kernel<<<Bb, FPS_T, fps_smem>>>(out);                                // #4 <- profiled

    prep_raw_kernel<<<(Bb * Nn * 32) / 256, 256>>>(points, W_raw, b_raw);    // #5
    prep_c3_kernel<<<(Bb * Mm * 64) / 256, 256>>>(conv3, W_c3, b_c3);        // #6
    post_kernel<<<1024 + Bb * Kk, 256>>>(spatial);                           // #7
    fuse_kernel<<<(Bb * Kk) / 16, 128>>>(W_fuse, bn_g, bn_b, bn_m, bn_v, out);  // #8
}